// round 11
// baseline (speedup 1.0000x reference)
#include <cuda_runtime.h>
#include <cstdint>

#define BATCH    64
#define SEQ      8192
#define RDIM     80
#define RING     169
#define RINGF    (RING * RDIM)     // 13520 floats
#define NTHREADS 320
#define PBUFS    4                 // partial ring depth (retime distance 3)

typedef unsigned long long u64;

__device__ __forceinline__ u64 ffma2(u64 a, u64 b, u64 c) {
    u64 d;
    asm("fma.rn.f32x2 %0, %1, %2, %3;" : "=l"(d) : "l"(a), "l"(b), "l"(c));
    return d;
}
__device__ __forceinline__ u64 fadd2(u64 a, u64 b) {
    u64 d;
    asm("add.rn.f32x2 %0, %1, %2;" : "=l"(d) : "l"(a), "l"(b));
    return d;
}
__device__ __forceinline__ float2 unpack2(u64 v) {
    unsigned lo, hi;
    asm("mov.b64 {%0, %1}, %2;" : "=r"(lo), "=r"(hi) : "l"(v));
    float2 r; r.x = __uint_as_float(lo); r.y = __uint_as_float(hi);
    return r;
}
__device__ __forceinline__ float fast_tanh(float v) {
    v = fminf(fmaxf(v, -15.0f), 15.0f);
    float u = __expf(-2.0f * v);
    return __fdividef(1.0f - u, 1.0f + u);
}

#define BAR() asm volatile("bar.sync 0, %0;" :: "n"(NTHREADS) : "memory")

// One 20-MAC quarter: 5 x LDS.128 + 10 FFMA2 into chains a0..a3
#define QUARTER_ACC(W, ptr)                                                \
    do {                                                                   \
        const ulonglong2* hv = reinterpret_cast<const ulonglong2*>(ptr);   \
        ulonglong2 h01 = hv[0], h23 = hv[1], h45 = hv[2];                  \
        ulonglong2 h67 = hv[3], h89 = hv[4];                               \
        a0 = ffma2(h01.x, (W)[0], a0); a1 = ffma2(h01.y, (W)[1], a1);      \
        a2 = ffma2(h23.x, (W)[2], a2); a3 = ffma2(h23.y, (W)[3], a3);      \
        a0 = ffma2(h45.x, (W)[4], a0); a1 = ffma2(h45.y, (W)[5], a1);      \
        a2 = ffma2(h67.x, (W)[6], a2); a3 = ffma2(h67.y, (W)[7], a3);      \
        a0 = ffma2(h89.x, (W)[8], a0); a1 = ffma2(h89.y, (W)[9], a1);      \
    } while (0)

__device__ __forceinline__ int tau_of(int k) {
    return (k == 0) ? 4 : (k == 1) ? 24 : (k == 2) ? 96 : 168;
}

__global__ __launch_bounds__(NTHREADS, 1)
void reservoir_kernel(const float* __restrict__ x,
                      const float* __restrict__ Win,
                      const float* __restrict__ Wfb,
                      const float* __restrict__ bias,
                      float* __restrict__ out)
{
    extern __shared__ float sm[];
    float* Hring = sm;                     // [RING][RDIM]
    float* xs    = Hring + RINGF;          // [SEQ]
    float* part  = xs + SEQ;               // [PBUFS][320], part[buf][i*4 + role]

    const int b   = blockIdx.x;
    const int tid = threadIdx.x;
    const int wid = tid >> 5;
    const int sub = tid & 1;

    for (int idx = tid; idx < RINGF; idx += NTHREADS) Hring[idx] = 0.0f;
    for (int idx = tid; idx < PBUFS * NTHREADS; idx += NTHREADS) part[idx] = 0.0f;
    const float* xb = x + (size_t)b * SEQ;
    for (int idx = tid; idx < SEQ; idx += NTHREADS) xs[idx] = xb[idx];

    float* outb = out + (size_t)b * SEQ * RDIM;
    const float* const ring_end = Hring + RINGF;
    float* const part_end = part + PBUFS * NTHREADS;

    __syncthreads();

    if (wid < 5) {
        // ================== Y warps: tau=1 + update + 3 old-tap quarters ==
        const int i  = tid >> 1;           // neuron 0..79
        const int g0 = 10 + 3 * sub;       // quarters C: 10..12, D: 13..15

        // old-tap quarter weights + initial h-row pointers
        u64 WX[3][10];
        const float* xp[3];
#pragma unroll
        for (int u = 0; u < 3; u++) {
            int g = g0 + u, k = g >> 2, q = g & 3;
            const float* wrow = Wfb + ((size_t)(k + 1) * RDIM + i) * RDIM + q * 20;
#pragma unroll
            for (int p = 0; p < 10; p++) {
                unsigned lo = __float_as_uint(wrow[2 * p]);
                unsigned hi = __float_as_uint(wrow[2 * p + 1]);
                WX[u][p] = ((u64)hi << 32) | (u64)lo;
            }
            int slot = (3 - tau_of(k) + 2 * RING) % RING;   // h[t+3-tau] at t=0
            xp[u] = Hring + slot * RDIM + q * 20;
        }

        // tau=1 half-row weights (40 floats)
        u64 WY[20];
        {
            const float* wr = Wfb + (size_t)i * RDIM + sub * 40;
#pragma unroll
            for (int p = 0; p < 20; p++) {
                unsigned lo = __float_as_uint(wr[2 * p]);
                unsigned hi = __float_as_uint(wr[2 * p + 1]);
                WY[p] = ((u64)hi << 32) | (u64)lo;
            }
        }
        const float win_i = Win[i], bias_i = bias[i];
        float h_i = 0.0f;

        const float* hY = Hring + (RING - 1) * RDIM + sub * 40;   // h[t-1]
        float* hw = Hring + i;                 // write slot t (lane sub==0)
        float* op = outb + i;                  // out row t (lane sub==1)
        const float* pr = part + i * 4;        // partials(t), buf t&3
        float* pw = part + 3 * NTHREADS + i * 4 + 2 + sub;  // partials(t+3)

#pragma unroll 1
        for (int t = 0; t < SEQ; ++t) {
            // prefetch (visible since bar(t-3) / setup)
            float4 p4  = *reinterpret_cast<const float4*>(pr);
            float  x_t = xs[t];

            // ---- tau=1 half matvec vs h[t-1] (broadcast LDS.128)
            u64 y0 = 0ull, y1 = 0ull, y2 = 0ull, y3 = 0ull;
            {
                const ulonglong2* hv = reinterpret_cast<const ulonglong2*>(hY);
#pragma unroll
                for (int p = 0; p < 5; p++) {
                    ulonglong2 A = hv[2 * p], B = hv[2 * p + 1];
                    y0 = ffma2(A.x, WY[4 * p + 0], y0);
                    y1 = ffma2(A.y, WY[4 * p + 1], y1);
                    y2 = ffma2(B.x, WY[4 * p + 2], y2);
                    y3 = ffma2(B.y, WY[4 * p + 3], y3);
                }
            }
            float2 yf = unpack2(fadd2(fadd2(y0, y1), fadd2(y2, y3)));
            float fh = yf.x + yf.y;
            fh += __shfl_xor_sync(0xffffffffu, fh, 1);    // join two halves

            float f   = fh + ((p4.x + p4.y) + (p4.z + p4.w));
            float val = fmaf(x_t, win_i, f + bias_i);
            h_i = 0.7f * h_i + 0.3f * fast_tanh(val);

            if (sub == 0) *hw = h_i;     // publish h[t] to ring
            else          *op = h_i;     // stream h[t] to gmem

            // ---- 3 old-tap quarters for step t+3 (need h[t-1] and older)
            u64 a0 = 0ull, a1 = 0ull, a2 = 0ull, a3 = 0ull;
            QUARTER_ACC(WX[0], xp[0]);
            QUARTER_ACC(WX[1], xp[1]);
            QUARTER_ACC(WX[2], xp[2]);
            float2 sf = unpack2(fadd2(fadd2(a0, a1), fadd2(a2, a3)));
            *pw = sf.x + sf.y;

            // ---- advance pointers (ring wrap)
            hY += RDIM; if (hY >= ring_end) hY -= RINGF;
            hw += RDIM; if (hw >= ring_end) hw -= RINGF;
            op += RDIM;
#pragma unroll
            for (int u = 0; u < 3; u++) {
                xp[u] += RDIM; if (xp[u] >= ring_end) xp[u] -= RINGF;
            }
            pr += NTHREADS; if (pr >= part_end) pr -= PBUFS * NTHREADS;
            pw += NTHREADS; if (pw >= part_end) pw -= PBUFS * NTHREADS;

            BAR();   // publishes h[t] and partials(t+3)
        }
    } else {
        // ================== producer warps: 5 old-tap quarters ==========
        const int i  = (tid - 160) >> 1;   // neuron 0..79
        const int g0 = 5 * sub;            // A: 0..4, B: 5..9

        u64 WX[5][10];
        const float* xp[5];
#pragma unroll
        for (int u = 0; u < 5; u++) {
            int g = g0 + u, k = g >> 2, q = g & 3;
            const float* wrow = Wfb + ((size_t)(k + 1) * RDIM + i) * RDIM + q * 20;
#pragma unroll
            for (int p = 0; p < 10; p++) {
                unsigned lo = __float_as_uint(wrow[2 * p]);
                unsigned hi = __float_as_uint(wrow[2 * p + 1]);
                WX[u][p] = ((u64)hi << 32) | (u64)lo;
            }
            int slot = (3 - tau_of(k) + 2 * RING) % RING;
            xp[u] = Hring + slot * RDIM + q * 20;
        }

        float* pw = part + 3 * NTHREADS + i * 4 + sub;   // roles A=0, B=1

#pragma unroll 1
        for (int t = 0; t < SEQ; ++t) {
            u64 a0 = 0ull, a1 = 0ull, a2 = 0ull, a3 = 0ull;
            QUARTER_ACC(WX[0], xp[0]);
            QUARTER_ACC(WX[1], xp[1]);
            QUARTER_ACC(WX[2], xp[2]);
            QUARTER_ACC(WX[3], xp[3]);
            QUARTER_ACC(WX[4], xp[4]);
            float2 sf = unpack2(fadd2(fadd2(a0, a1), fadd2(a2, a3)));
            *pw = sf.x + sf.y;

#pragma unroll
            for (int u = 0; u < 5; u++) {
                xp[u] += RDIM; if (xp[u] >= ring_end) xp[u] -= RINGF;
            }
            pw += NTHREADS; if (pw >= part_end) pw -= PBUFS * NTHREADS;

            BAR();
        }
    }
}

extern "C" void kernel_launch(void* const* d_in, const int* in_sizes, int n_in,
                              void* d_out, int out_size)
{
    const float* x    = (const float*)d_in[0];  // [64, 8192, 1]
    const float* Win  = (const float*)d_in[1];  // [80, 1]
    const float* Wfb  = (const float*)d_in[2];  // [5, 80, 80]
    const float* bias = (const float*)d_in[3];  // [80]
    float* out = (float*)d_out;                 // [64, 8192, 80]

    const int smem_bytes = (RINGF + SEQ + PBUFS * NTHREADS) * sizeof(float);
    cudaFuncSetAttribute(reservoir_kernel,
                         cudaFuncAttributeMaxDynamicSharedMemorySize, smem_bytes);

    reservoir_kernel<<<BATCH, NTHREADS, smem_bytes>>>(x, Win, Wfb, bias, out);
}